// round 1
// baseline (speedup 1.0000x reference)
#include <cuda_runtime.h>
#include <math.h>

// Problem constants (fixed shapes for this problem instance)
#define T_ 4096
#define B_ 4
#define E_ 512
#define CK_ 1024
#define H_ 8
#define HD_ 64

// Scratch (allocation-free rule: __device__ globals)
__device__ float g_q  [(size_t)T_ * B_ * E_];   // 32 MB
__device__ float g_kin[(size_t)CK_ * B_ * E_];  // 8 MB
__device__ float g_vin[(size_t)CK_ * B_ * E_];
__device__ float g_k  [(size_t)CK_ * B_ * E_];
__device__ float g_v  [(size_t)CK_ * B_ * E_];
__device__ float g_att[(size_t)T_ * B_ * E_];   // 32 MB

// ---------------------------------------------------------------------------
// SGEMM: C[M,N] = (A[M,K] * op(B) + bias) * scale
//   TRANS_B=true : B is [N,K] row-major (C += A·Bᵀ)   — "NT"
//   TRANS_B=false: B is [K,N] row-major (C += A·B)    — "NN"
// Tiles: 128x128x16, 256 threads, 8x8 per thread.
// Requires M%128==0, N%128==0, K%16==0 (true for all stages here).
// ---------------------------------------------------------------------------
template<bool TRANS_B, bool HAS_BIAS>
__global__ __launch_bounds__(256, 2) void sgemm_kernel(
    const float* __restrict__ A, const float* __restrict__ Bm,
    const float* __restrict__ bias, float* __restrict__ C,
    int M, int N, int K, float scale)
{
    __shared__ float As[16][132];   // staged transposed: As[k][m], pad vs store conflicts
    __shared__ float Bs[16][132];   // Bs[k][n]

    const int tid = threadIdx.x;
    const int tx = tid & 15;   // column group: cols tx + 16*j
    const int ty = tid >> 4;   // row group:    rows ty*8 + i
    const int m0 = blockIdx.y * 128;
    const int n0 = blockIdx.x * 128;

    float acc[8][8];
#pragma unroll
    for (int i = 0; i < 8; i++)
#pragma unroll
        for (int j = 0; j < 8; j++) acc[i][j] = 0.f;

    for (int k0 = 0; k0 < K; k0 += 16) {
        // ---- stage A tile (128 rows x 16 k), float4 along K, store transposed
#pragma unroll
        for (int l = 0; l < 2; l++) {
            int idx = tid + l * 256;          // 0..511
            int row = idx >> 2;               // 0..127
            int c4  = (idx & 3) << 2;         // 0,4,8,12
            float4 a = *(const float4*)(A + (size_t)(m0 + row) * K + k0 + c4);
            As[c4 + 0][row] = a.x; As[c4 + 1][row] = a.y;
            As[c4 + 2][row] = a.z; As[c4 + 3][row] = a.w;
        }
        // ---- stage B tile
        if (TRANS_B) {
#pragma unroll
            for (int l = 0; l < 2; l++) {
                int idx = tid + l * 256;
                int row = idx >> 2;           // n index 0..127
                int c4  = (idx & 3) << 2;
                float4 b = *(const float4*)(Bm + (size_t)(n0 + row) * K + k0 + c4);
                Bs[c4 + 0][row] = b.x; Bs[c4 + 1][row] = b.y;
                Bs[c4 + 2][row] = b.z; Bs[c4 + 3][row] = b.w;
            }
        } else {
#pragma unroll
            for (int l = 0; l < 2; l++) {
                int idx = tid + l * 256;      // 16 rows x 32 float4
                int row = idx >> 5;           // k row 0..15
                int c4  = (idx & 31) << 2;    // 0..124
                float4 b = *(const float4*)(Bm + (size_t)(k0 + row) * N + n0 + c4);
                *(float4*)&Bs[row][c4] = b;
            }
        }
        __syncthreads();

        // ---- 8x8 micro-kernel
#pragma unroll
        for (int kk = 0; kk < 16; kk++) {
            float a[8], b[8];
            *(float4*)&a[0] = *(const float4*)&As[kk][ty * 8];
            *(float4*)&a[4] = *(const float4*)&As[kk][ty * 8 + 4];
#pragma unroll
            for (int j = 0; j < 8; j++) b[j] = Bs[kk][tx + 16 * j];
#pragma unroll
            for (int i = 0; i < 8; i++)
#pragma unroll
                for (int j = 0; j < 8; j++)
                    acc[i][j] = fmaf(a[i], b[j], acc[i][j]);
        }
        __syncthreads();
    }

    // ---- epilogue: (acc + bias) * scale, scalar coalesced stores
#pragma unroll
    for (int i = 0; i < 8; i++) {
        size_t crow = (size_t)(m0 + ty * 8 + i) * N + n0;
#pragma unroll
        for (int j = 0; j < 8; j++) {
            int n = tx + 16 * j;
            float v = acc[i][j];
            if (HAS_BIAS) v += bias[n0 + n];
            C[crow + n] = v * scale;
        }
    }
}

// ---------------------------------------------------------------------------
// Flash attention, per-head: q[T,64] x k[CK,64] -> softmax -> x v[CK,64]
// grid = (T/64, B*H); block = 256 threads; online softmax over CK in 64-key tiles.
// Q/K/V head slices are contiguous 64 floats at offset ((l*B+b)*E + h*64).
// Thread layout: tx = lane col group (16), ty = row group (16).
//   rows  owned: ty + 16*i (i<4)     -> reductions across the 16 tx lanes (half-warp shfl)
//   score cols : tx + 16*j (j<4)     -> K smem reads ~2-way conflict w/ PAD=68
//   out   cols : tx*4 + j            -> float4 V reads & float4 O stores
// ---------------------------------------------------------------------------
__device__ __forceinline__ float redmax16(float v) {
    v = fmaxf(v, __shfl_xor_sync(0xffffffffu, v, 1));
    v = fmaxf(v, __shfl_xor_sync(0xffffffffu, v, 2));
    v = fmaxf(v, __shfl_xor_sync(0xffffffffu, v, 4));
    v = fmaxf(v, __shfl_xor_sync(0xffffffffu, v, 8));
    return v;
}
__device__ __forceinline__ float redsum16(float v) {
    v += __shfl_xor_sync(0xffffffffu, v, 1);
    v += __shfl_xor_sync(0xffffffffu, v, 2);
    v += __shfl_xor_sync(0xffffffffu, v, 4);
    v += __shfl_xor_sync(0xffffffffu, v, 8);
    return v;
}

__global__ __launch_bounds__(256) void flash_kernel(
    const float* __restrict__ Q, const float* __restrict__ Kb,
    const float* __restrict__ Vb, float* __restrict__ O)
{
    extern __shared__ float sm[];
    constexpr int PAD = 68;               // 272B row stride: 16B-aligned, breaks bank repeat
    float* Qs = sm;                       // [64][PAD]
    float* Ks = sm + 64 * PAD;            // [64][PAD], reused as P after scores
    float* Vs = sm + 2 * 64 * PAD;        // [64][PAD]

    const int tid = threadIdx.x;
    const int tx = tid & 15;
    const int ty = tid >> 4;
    const int bh = blockIdx.y;
    const int b  = bh >> 3;               // bh = b*H + h
    const int h  = bh & 7;
    const int t0 = blockIdx.x * 64;

    // load Q tile: 64 rows x 64 floats
#pragma unroll
    for (int l = 0; l < 4; l++) {
        int idx = tid + l * 256;          // 1024 float4
        int r  = idx >> 4;
        int c4 = (idx & 15) << 2;
        *(float4*)&Qs[r * PAD + c4] =
            *(const float4*)(Q + ((size_t)(t0 + r) * B_ + b) * E_ + h * 64 + c4);
    }

    float m_run[4], l_run[4], o_acc[4][4];
#pragma unroll
    for (int i = 0; i < 4; i++) {
        m_run[i] = -1e30f; l_run[i] = 0.f;
#pragma unroll
        for (int j = 0; j < 4; j++) o_acc[i][j] = 0.f;
    }
    __syncthreads();

    for (int kt = 0; kt < CK_ / 64; kt++) {
        // ---- load K and V tiles
#pragma unroll
        for (int l = 0; l < 4; l++) {
            int idx = tid + l * 256;
            int r  = idx >> 4;
            int c4 = (idx & 15) << 2;
            size_t g = ((size_t)(kt * 64 + r) * B_ + b) * E_ + h * 64 + c4;
            *(float4*)&Ks[r * PAD + c4] = *(const float4*)(Kb + g);
            *(float4*)&Vs[r * PAD + c4] = *(const float4*)(Vb + g);
        }
        __syncthreads();

        // ---- scores s[i][j] = q_row(ty+16i) . k_row(tx+16j)
        float s[4][4];
#pragma unroll
        for (int i = 0; i < 4; i++)
#pragma unroll
            for (int j = 0; j < 4; j++) s[i][j] = 0.f;

#pragma unroll
        for (int d = 0; d < 64; d += 4) {
            float4 q4[4], k4[4];
#pragma unroll
            for (int i = 0; i < 4; i++)
                q4[i] = *(const float4*)&Qs[(ty + 16 * i) * PAD + d];
#pragma unroll
            for (int j = 0; j < 4; j++)
                k4[j] = *(const float4*)&Ks[(tx + 16 * j) * PAD + d];
#pragma unroll
            for (int i = 0; i < 4; i++)
#pragma unroll
                for (int j = 0; j < 4; j++) {
                    s[i][j] = fmaf(q4[i].x, k4[j].x, s[i][j]);
                    s[i][j] = fmaf(q4[i].y, k4[j].y, s[i][j]);
                    s[i][j] = fmaf(q4[i].z, k4[j].z, s[i][j]);
                    s[i][j] = fmaf(q4[i].w, k4[j].w, s[i][j]);
                }
        }

        // ---- online softmax update
        float p[4][4];
#pragma unroll
        for (int i = 0; i < 4; i++) {
            float mn = fmaxf(fmaxf(s[i][0], s[i][1]), fmaxf(s[i][2], s[i][3]));
            mn = redmax16(mn);
            mn = fmaxf(mn, m_run[i]);
            float rs = 0.f;
#pragma unroll
            for (int j = 0; j < 4; j++) {
                p[i][j] = __expf(s[i][j] - mn);
                rs += p[i][j];
            }
            rs = redsum16(rs);
            float f = __expf(m_run[i] - mn);
            l_run[i] = l_run[i] * f + rs;
            m_run[i] = mn;
#pragma unroll
            for (int j = 0; j < 4; j++) o_acc[i][j] *= f;
        }
        __syncthreads();     // everyone done reading Ks (scores)

        // ---- write P into the K buffer: Ps[row][key]
#pragma unroll
        for (int i = 0; i < 4; i++)
#pragma unroll
            for (int j = 0; j < 4; j++)
                Ks[(ty + 16 * i) * PAD + tx + 16 * j] = p[i][j];
        __syncthreads();

        // ---- o += P @ V : o[row][c], c = tx*4 + {0..3}
#pragma unroll
        for (int k = 0; k < 64; k += 4) {
            float4 v4[4], p4[4];
#pragma unroll
            for (int kk = 0; kk < 4; kk++)
                v4[kk] = *(const float4*)&Vs[(k + kk) * PAD + tx * 4];
#pragma unroll
            for (int i = 0; i < 4; i++)
                p4[i] = *(const float4*)&Ks[(ty + 16 * i) * PAD + k];
#pragma unroll
            for (int i = 0; i < 4; i++) {
                o_acc[i][0] = fmaf(p4[i].x, v4[0].x, o_acc[i][0]);
                o_acc[i][1] = fmaf(p4[i].x, v4[0].y, o_acc[i][1]);
                o_acc[i][2] = fmaf(p4[i].x, v4[0].z, o_acc[i][2]);
                o_acc[i][3] = fmaf(p4[i].x, v4[0].w, o_acc[i][3]);
                o_acc[i][0] = fmaf(p4[i].y, v4[1].x, o_acc[i][0]);
                o_acc[i][1] = fmaf(p4[i].y, v4[1].y, o_acc[i][1]);
                o_acc[i][2] = fmaf(p4[i].y, v4[1].z, o_acc[i][2]);
                o_acc[i][3] = fmaf(p4[i].y, v4[1].w, o_acc[i][3]);
                o_acc[i][0] = fmaf(p4[i].z, v4[2].x, o_acc[i][0]);
                o_acc[i][1] = fmaf(p4[i].z, v4[2].y, o_acc[i][1]);
                o_acc[i][2] = fmaf(p4[i].z, v4[2].z, o_acc[i][2]);
                o_acc[i][3] = fmaf(p4[i].z, v4[2].w, o_acc[i][3]);
                o_acc[i][0] = fmaf(p4[i].w, v4[3].x, o_acc[i][0]);
                o_acc[i][1] = fmaf(p4[i].w, v4[3].y, o_acc[i][1]);
                o_acc[i][2] = fmaf(p4[i].w, v4[3].z, o_acc[i][2]);
                o_acc[i][3] = fmaf(p4[i].w, v4[3].w, o_acc[i][3]);
            }
        }
        __syncthreads();     // before next tile overwrites Ks/Vs
    }

    // ---- normalize and write
#pragma unroll
    for (int i = 0; i < 4; i++) {
        float inv = 1.f / l_run[i];
        int r = ty + 16 * i;
        float4 w = make_float4(o_acc[i][0] * inv, o_acc[i][1] * inv,
                               o_acc[i][2] * inv, o_acc[i][3] * inv);
        *(float4*)(O + ((size_t)(t0 + r) * B_ + b) * E_ + h * 64 + tx * 4) = w;
    }
}

// ---------------------------------------------------------------------------
extern "C" void kernel_launch(void* const* d_in, const int* in_sizes, int n_in,
                              void* d_out, int out_size)
{
    const float* query = (const float*)d_in[0];
    const float* Wq    = (const float*)d_in[1];
    const float* bq    = (const float*)d_in[2];
    const float* Wk    = (const float*)d_in[3];
    const float* bk    = (const float*)d_in[4];
    const float* Wv    = (const float*)d_in[5];
    const float* bv    = (const float*)d_in[6];
    const float* Wck   = (const float*)d_in[7];
    const float* Wcv   = (const float*)d_in[8];
    const float* Wo    = (const float*)d_in[9];
    const float* bo    = (const float*)d_in[10];
    float* out = (float*)d_out;

    float *q, *kin, *vin, *k, *v, *att;
    cudaGetSymbolAddress((void**)&q,   g_q);
    cudaGetSymbolAddress((void**)&kin, g_kin);
    cudaGetSymbolAddress((void**)&vin, g_vin);
    cudaGetSymbolAddress((void**)&k,   g_k);
    cudaGetSymbolAddress((void**)&v,   g_v);
    cudaGetSymbolAddress((void**)&att, g_att);

    dim3 blk(256);
    const float qscale = 0.125f;  // hd^-0.5 = 64^-0.5

    // 1) q = (X @ Wq^T + bq) * scale        [16384 x 512 x 512]
    sgemm_kernel<true, true><<<dim3(E_ / 128, (T_ * B_) / 128), blk>>>(
        query, Wq, bq, q, T_ * B_, E_, E_, qscale);

    // 2) k_in = Wck @ X_flat  (NN)          [1024 x 2048 x 4096]
    sgemm_kernel<false, false><<<dim3((B_ * E_) / 128, CK_ / 128), blk>>>(
        Wck, query, nullptr, kin, CK_, B_ * E_, T_, 1.f);

    // 3) v_in = Wcv @ X_flat  (NN)
    sgemm_kernel<false, false><<<dim3((B_ * E_) / 128, CK_ / 128), blk>>>(
        Wcv, query, nullptr, vin, CK_, B_ * E_, T_, 1.f);

    // 4) k = k_in @ Wk^T + bk               [4096 x 512 x 512]
    sgemm_kernel<true, true><<<dim3(E_ / 128, (CK_ * B_) / 128), blk>>>(
        kin, Wk, bk, k, CK_ * B_, E_, E_, 1.f);

    // 5) v = v_in @ Wv^T + bv
    sgemm_kernel<true, true><<<dim3(E_ / 128, (CK_ * B_) / 128), blk>>>(
        vin, Wv, bv, v, CK_ * B_, E_, E_, 1.f);

    // 6) attention (fused flash over CK)
    const int shbytes = 3 * 64 * 68 * (int)sizeof(float);  // 52224 B
    cudaFuncSetAttribute(flash_kernel,
                         cudaFuncAttributeMaxDynamicSharedMemorySize, shbytes);
    flash_kernel<<<dim3(T_ / 64, B_ * H_), blk, shbytes>>>(q, k, v, att);

    // 7) out = att @ Wo^T + bo              [16384 x 512 x 512]
    sgemm_kernel<true, true><<<dim3(E_ / 128, (T_ * B_) / 128), blk>>>(
        att, Wo, bo, out, T_ * B_, E_, E_, 1.f);

    (void)in_sizes; (void)n_in; (void)out_size;
}